// round 13
// baseline (speedup 1.0000x reference)
#include <cuda_runtime.h>
#include <cuda_fp16.h>
#include <cstdint>

#define NB 4096
#define NT 168
#define NH 128
#define NG 512
#define NO 24

// ------------------------- device scratch -------------------------
__device__ __half g_ench[NB * NT * NH];  // encoder hidden states (B*T, H) fp16
__device__ __half g_Ueh [NB * NT * NH];  // Ua @ enc_outs        (B*T, H) fp16
__device__ float g_h  [NB * NH];
__device__ float g_c  [NB * NH];
__device__ __half g_WencP[8 * 8 * 8 * 32 * 4];  // enc Whh B-frags [wid][kt][j][lane][4]
__device__ __half g_UaP  [16 * 8 * 32 * 4];     // Ua B-frags [nt][kt][lane][4]
__device__ __half g_WaP  [16 * 8 * 32 * 4];     // Wa B-frags [nt][kt][lane][4]
__device__ __half g_WdP  [8 * 16 * 8 * 32 * 4]; // dec [Wih(ctx)|Whh] B-frags, K=256
__device__ float g_encBp[NG];           // enc bias, n = u*4+gate
__device__ float g_wihp [NG];           // enc Wih,  n = u*4+gate
__device__ float g_decBp[NG];           // dec bias, n = u*4+gate
__device__ float g_dinW [NG];           // dec Wih col 0 (din), n = u*4+gate

// fast activations
__device__ __forceinline__ float ftanh_fast(float x) { asm("tanh.approx.f32 %0, %0;" : "+f"(x)); return x; }
__device__ __forceinline__ float fsig_fast(float x)  { return 0.5f + 0.5f * ftanh_fast(0.5f * x); }
__device__ __forceinline__ __half2 htanh2(__half2 x) {
    uint32_t v = *(uint32_t*)&x;
    asm("tanh.approx.f16x2 %0, %0;" : "+r"(v));
    return *(__half2*)&v;
}

// ------------------------- mma helpers -------------------------
__device__ __forceinline__ void ldmA(uint32_t a[4], const __half* p) {
    uint32_t addr = (uint32_t)__cvta_generic_to_shared(p);
    asm volatile("ldmatrix.sync.aligned.m8n8.x4.shared.b16 {%0,%1,%2,%3}, [%4];"
        : "=r"(a[0]), "=r"(a[1]), "=r"(a[2]), "=r"(a[3]) : "r"(addr));
}
__device__ __forceinline__ void mma16816(float c[4], const uint32_t a[4], uint2 b) {
    asm volatile("mma.sync.aligned.m16n8k16.row.col.f32.f16.f16.f32 "
        "{%0,%1,%2,%3},{%4,%5,%6,%7},{%8,%9},{%0,%1,%2,%3};"
        : "+f"(c[0]), "+f"(c[1]), "+f"(c[2]), "+f"(c[3])
        : "r"(a[0]), "r"(a[1]), "r"(a[2]), "r"(a[3]), "r"(b.x), "r"(b.y));
}

// ------------------------- weight packing -------------------------
__global__ void pack_kernel(const float* __restrict__ encWih,
                            const float* __restrict__ encWhh,
                            const float* __restrict__ encBih, const float* __restrict__ encBhh,
                            const float* __restrict__ Wa, const float* __restrict__ Ua,
                            const float* __restrict__ decWih, const float* __restrict__ decWhh,
                            const float* __restrict__ decBih, const float* __restrict__ decBhh)
{
    int stride = gridDim.x * blockDim.x;
    int i0 = blockIdx.x * blockDim.x + threadIdx.x;

    for (int idx = i0; idx < 8 * 8 * 8 * 32 * 4; idx += stride) {
        int q = idx & 3, lane = (idx >> 2) & 31;
        int rest = idx >> 7;
        int j = rest & 7, kt = (rest >> 3) & 7, wid = rest >> 6;
        int g = lane >> 2, tg = lane & 3;
        int n = wid * 64 + j * 8 + g;
        int u = n >> 2, gate = n & 3;
        int k = kt * 16 + ((q < 2) ? (tg * 2 + q) : (tg * 2 + 8 + (q - 2)));
        g_WencP[idx] = __float2half_rn(encWhh[(gate * 128 + u) * NH + k]);
    }
    for (int idx = i0; idx < 8 * 16 * 8 * 32 * 4; idx += stride) {
        int q = idx & 3, lane = (idx >> 2) & 31;
        int rest = idx >> 7;
        int j = rest & 7, kt = (rest >> 3) & 15, wid = rest >> 7;
        int g = lane >> 2, tg = lane & 3;
        int n = wid * 64 + j * 8 + g;
        int u = n >> 2, gate = n & 3;
        int k = kt * 16 + ((q < 2) ? (tg * 2 + q) : (tg * 2 + 8 + (q - 2)));
        float v = (k < NH) ? decWih[(gate * 128 + u) * (NH + 1) + 1 + k]
                           : decWhh[(gate * 128 + u) * NH + (k - NH)];
        g_WdP[idx] = __float2half_rn(v);
    }
    for (int idx = i0; idx < 16 * 8 * 32 * 4; idx += stride) {
        int q = idx & 3, lane = (idx >> 2) & 31;
        int rest = idx >> 7;
        int kt = rest & 7, nt = rest >> 3;
        int g = lane >> 2, tg = lane & 3;
        int n = nt * 8 + g;
        int k = kt * 16 + ((q < 2) ? (tg * 2 + q) : (tg * 2 + 8 + (q - 2)));
        g_UaP[idx] = __float2half_rn(Ua[n * NH + k]);
        g_WaP[idx] = __float2half_rn(Wa[n * NH + k]);
    }
    for (int i = i0; i < NG; i += stride) {
        int u = i >> 2, gate = i & 3;
        g_encBp[i] = encBih[gate * 128 + u] + encBhh[gate * 128 + u];
        g_wihp[i]  = encWih[gate * 128 + u];
        g_decBp[i] = decBih[gate * 128 + u] + decBhh[gate * 128 + u];
        g_dinW[i]  = decWih[(gate * 128 + u) * (NH + 1)];
    }
}

// ------------------------- encoder + fused Ue (HMMA, one launch, 168 steps) -----------------
// 16 rows/block, grid 256. Per step: gate HMMA (8 warps x 64 n-cols), LSTM epilogue,
// Ue HMMA (warp w -> units [16w,16w+16)), coalesced store of h_t and Ue_t.
__global__ void __launch_bounds__(256) enc_kernel(const float* __restrict__ x)
{
    __shared__ __half hsh[16][136];
    __shared__ __half uesh[16][136];
    __shared__ float biassh[NG], wihsh[NG];
    int tid = threadIdx.x;
    int wid = tid >> 5, lane = tid & 31;
    int b0 = blockIdx.x * 16;
    int g = lane >> 2, tg = lane & 3, tg2 = tg >> 1;
    int odd = tg & 1;
    int lrow = lane & 15;
    int lcol = (lane >> 4) << 3;
    int myrow = g + (odd ? 8 : 0);

    for (int i = tid; i < NG; i += 256) { biassh[i] = g_encBp[i]; wihsh[i] = g_wihp[i]; }
    for (int i = tid; i < 16 * 136; i += 256) ((__half*)hsh)[i] = __ushort_as_half(0);

    float creg[8];
    #pragma unroll
    for (int i = 0; i < 8; i++) creg[i] = 0.f;

    const uint2* wbase = ((const uint2*)g_WencP) + wid * 2048 + lane;
    const uint2* uaB = (const uint2*)g_UaP;
    int crow = tid >> 4, cch = tid & 15;    // copy indices (256 = 16x16)
    __syncthreads();

    for (int t = 0; t < NT; t++) {
        float xv = x[(b0 + myrow) * NT + t];

        float acc[8][4];
        #pragma unroll
        for (int j = 0; j < 8; j++)
            #pragma unroll
            for (int q = 0; q < 4; q++) acc[j][q] = 0.f;

        #pragma unroll
        for (int kt = 0; kt < 8; kt++) {
            uint32_t a[4];
            ldmA(a, &hsh[lrow][kt * 16 + lcol]);
            #pragma unroll
            for (int j = 0; j < 8; j++) {
                uint2 b = wbase[(kt * 8 + j) * 32];
                mma16816(acc[j], a, b);
            }
        }
        __syncthreads();   // gate-mma reads of hsh done

        #pragma unroll
        for (int j = 0; j < 8; j++) {
            float t0 = __shfl_xor_sync(0xffffffffu, acc[j][0], 1);
            float t1 = __shfl_xor_sync(0xffffffffu, acc[j][1], 1);
            float t2 = __shfl_xor_sync(0xffffffffu, acc[j][2], 1);
            float t3 = __shfl_xor_sync(0xffffffffu, acc[j][3], 1);
            float gi, gf, gg, go;
            if (!odd) { gi = acc[j][0]; gf = acc[j][1]; gg = t0; go = t1; }
            else      { gi = t2; gf = t3; gg = acc[j][2]; go = acc[j][3]; }
            int u = wid * 16 + j * 2 + tg2;
            float4 bi = *(const float4*)&biassh[u * 4];
            float4 wi = *(const float4*)&wihsh[u * 4];
            gi += bi.x + xv * wi.x;
            gf += bi.y + xv * wi.y;
            gg += bi.z + xv * wi.z;
            go += bi.w + xv * wi.w;
            float c = fsig_fast(gf) * creg[j] + fsig_fast(gi) * ftanh_fast(gg);
            creg[j] = c;
            float h = fsig_fast(go) * ftanh_fast(c);
            hsh[myrow][u] = __float2half_rn(h);
        }
        __syncthreads();   // hsh fully updated

        // Ue_t = h_t @ Ua^T : warp w -> units [16w, 16w+16)
        float uacc[2][4];
        #pragma unroll
        for (int nt = 0; nt < 2; nt++)
            #pragma unroll
            for (int q = 0; q < 4; q++) uacc[nt][q] = 0.f;
        #pragma unroll
        for (int kt = 0; kt < 8; kt++) {
            uint32_t a[4];
            ldmA(a, &hsh[lrow][kt * 16 + lcol]);
            #pragma unroll
            for (int nt = 0; nt < 2; nt++) {
                uint2 b = uaB[((wid * 2 + nt) * 8 + kt) * 32 + lane];
                mma16816(uacc[nt], a, b);
            }
        }
        #pragma unroll
        for (int nt = 0; nt < 2; nt++) {
            int n = wid * 16 + nt * 8 + tg * 2;
            *(__half2*)&uesh[g][n]     = __floats2half2_rn(uacc[nt][0], uacc[nt][1]);
            *(__half2*)&uesh[g + 8][n] = __floats2half2_rn(uacc[nt][2], uacc[nt][3]);
        }
        __syncthreads();   // uesh staged

        // coalesced stores of h_t and Ue_t (256 thr = 16 rows x 16 uint4)
        size_t base = (size_t)(b0 + crow) * (NT * NH) + (size_t)t * NH + cch * 8;
        *(uint4*)&g_ench[base] = *(uint4*)&hsh[crow][cch * 8];
        *(uint4*)&g_Ueh [base] = *(uint4*)&uesh[crow][cch * 8];
    }
    __syncthreads();
    for (int i = tid; i < 16 * NH; i += 256) {
        int r = i >> 7, u2 = i & 127;
        g_h[(b0 + r) * NH + u2] = __half2float(hsh[r][u2]);
    }
    #pragma unroll
    for (int j = 0; j < 8; j++) {
        int u = wid * 16 + j * 2 + tg2;
        g_c[(b0 + myrow) * NH + u] = creg[j];
    }
}

// ------------------------- fused decoder (ONE launch, L2-resident, fc overlapped) ----------
// grid 512 x 1024 thr = 32 warps, 8 rows/block, 1 block/SM; L2-resident stream (R11/R12).
// Phase1: warps 0-15 q-HMMA, warps 24-31 fc(step-1). 5 syncs/step.
__global__ void __launch_bounds__(1024, 1) dec_kernel(const float* __restrict__ x,
                                                      const float* __restrict__ va,
                                                      const float* __restrict__ fcW,
                                                      const float* __restrict__ fcb,
                                                      float* __restrict__ out)
{
    __shared__ __half ash[16][264];     // [row][ ctx fp16 (128) | h fp16 (128) ] rows 8..15 zero
    __shared__ float hsh[8][NH];        // h fp32 (fc)
    __shared__ float qsh[8][NH];        // q = h @ Wa^T
    __shared__ float cpart[8][4][NH];   // att partial contexts (row, quarter)
    __shared__ float zpart[8][4];
    __shared__ float biassh[NG], dinwsh[NG];
    __shared__ float dinsh[8];
    int tid = threadIdx.x;
    int wid = tid >> 5, lane = tid & 31;
    int b0 = blockIdx.x * 8;
    int g = lane >> 2, tg = lane & 3, tg2 = tg >> 1;
    int odd = tg & 1;
    int lrow = lane & 15;
    int lcol = (lane >> 4) << 3;
    int sub = lane & 15;
    int arow = wid >> 2, aq = wid & 3;          // att: row, T-quarter
    int wq = wid >> 2, j0 = (wid & 3) * 2;      // cell: 64-col group, 2 n8 tiles
    int myrow = g + (odd ? 8 : 0);              // cell epilogue row (valid if < 8)

    for (int i = tid; i < NG; i += 1024) { biassh[i] = g_decBp[i]; dinwsh[i] = g_dinW[i]; }
    for (int i = tid; i < 16 * 264; i += 1024) ((__half*)ash)[i] = __ushort_as_half(0);
    __syncthreads();
    for (int i = tid; i < 8 * NH; i += 1024) {
        int r = i >> 7, k = i & 127;
        float hv = g_h[(b0 + r) * NH + k];
        hsh[r][k] = hv;
        ash[r][128 + k] = __float2half_rn(hv);
    }
    float creg[2] = {0.f, 0.f};
    if (myrow < 8) {
        #pragma unroll
        for (int j = 0; j < 2; j++) {
            int u = wq * 16 + (j0 + j) * 2 + tg2;
            creg[j] = g_c[(b0 + myrow) * NH + u];
        }
    }
    if (tid < 8) dinsh[tid] = x[(b0 + tid) * NT + (NT - 1)];

    float4 va0 = *(const float4*)&va[sub * 8];
    float4 va1 = *(const float4*)&va[sub * 8 + 4];
    float fw0 = fcW[lane], fw1 = fcW[lane + 32], fw2 = fcW[lane + 64], fw3 = fcW[lane + 96];
    float fcbv = fcb[0];
    const uint4* uep = (const uint4*)(g_Ueh + (size_t)(b0 + arow) * NT * NH) + lane;
    const uint4* ep  = (const uint4*)(g_ench + (size_t)(b0 + arow) * NT * NH) + lane;
    const uint2* wbase = ((const uint2*)g_WdP) + wq * 4096 + lane;
    const uint2* wap   = ((const uint2*)g_WaP);
    __syncthreads();

    for (int step = 0; step < NO; step++) {
        // ---- phase1: q-HMMA (warps 0..15) || fc(step-1) (warps 24..31) ----
        if (wid < 16) {
            float qc[4] = {0.f, 0.f, 0.f, 0.f};
            #pragma unroll
            for (int kt = 0; kt < 8; kt++) {
                uint32_t a[4];
                ldmA(a, &ash[lrow][128 + kt * 16 + lcol]);
                uint2 b = wap[(wid * 8 + kt) * 32 + lane];
                mma16816(qc, a, b);
            }
            int m = lane >> 2;
            if (m < 8) {
                int ub = wid * 8 + (lane & 3) * 2;
                qsh[m][ub]     = qc[0];
                qsh[m][ub + 1] = qc[1];
            }
        } else if (wid >= 24 && step > 0) {
            int r = wid - 24;
            float s = hsh[r][lane] * fw0 + hsh[r][lane + 32] * fw1
                    + hsh[r][lane + 64] * fw2 + hsh[r][lane + 96] * fw3;
            #pragma unroll
            for (int off = 16; off > 0; off >>= 1) s += __shfl_xor_sync(0xffffffffu, s, off);
            if (lane == 0) {
                float p = s + fcbv;
                out[(b0 + r) * NO + (step - 1)] = p;
                dinsh[r] = p;
            }
        }
        __syncthreads();

        // ---- attention: 4 warps per row, 21 pair-iters each, f16x2 energy ----
        {
            float4 qaf = *(float4*)&qsh[arow][sub * 8];
            float4 qbf = *(float4*)&qsh[arow][sub * 8 + 4];
            __half2 qh0 = __floats2half2_rn(qaf.x, qaf.y);
            __half2 qh1 = __floats2half2_rn(qaf.z, qaf.w);
            __half2 qh2 = __floats2half2_rn(qbf.x, qbf.y);
            __half2 qh3 = __floats2half2_rn(qbf.z, qbf.w);
            float ca[8];
            #pragma unroll
            for (int j = 0; j < 8; j++) ca[j] = 0.f;
            float Z = 0.f;
            int ibeg = aq * 21;
            #pragma unroll 3
            for (int i = ibeg; i < ibeg + 21; i++) {
                uint4 ue = uep[i * 32];
                uint4 en = ep[i * 32];
                __half2 t0 = htanh2(__hadd2(*(__half2*)&ue.x, qh0));
                __half2 t1 = htanh2(__hadd2(*(__half2*)&ue.y, qh1));
                __half2 t2 = htanh2(__hadd2(*(__half2*)&ue.z, qh2));
                __half2 t3 = htanh2(__hadd2(*(__half2*)&ue.w, qh3));
                float2 f0 = __half22float2(t0);
                float2 f1 = __half22float2(t1);
                float2 f2 = __half22float2(t2);
                float2 f3 = __half22float2(t3);
                float s = f0.x * va0.x + f0.y * va0.y + f1.x * va0.z + f1.y * va0.w
                        + f2.x * va1.x + f2.y * va1.y + f3.x * va1.z + f3.y * va1.w;
                s += __shfl_xor_sync(0xffffffffu, s, 8);
                s += __shfl_xor_sync(0xffffffffu, s, 4);
                s += __shfl_xor_sync(0xffffffffu, s, 2);
                s += __shfl_xor_sync(0xffffffffu, s, 1);
                float w = __expf(s);
                Z += w;
                float2 n0 = __half22float2(*(__half2*)&en.x);
                float2 n1 = __half22float2(*(__half2*)&en.y);
                float2 n2 = __half22float2(*(__half2*)&en.z);
                float2 n3 = __half22float2(*(__half2*)&en.w);
                ca[0] += w * n0.x; ca[1] += w * n0.y;
                ca[2] += w * n1.x; ca[3] += w * n1.y;
                ca[4] += w * n2.x; ca[5] += w * n2.y;
                ca[6] += w * n3.x; ca[7] += w * n3.y;
            }
            Z += __shfl_xor_sync(0xffffffffu, Z, 16);
            #pragma unroll
            for (int j = 0; j < 8; j++) ca[j] += __shfl_xor_sync(0xffffffffu, ca[j], 16);
            if (lane == 0) zpart[arow][aq] = Z;
            if (lane < 16) {
                *(float4*)&cpart[arow][aq][sub * 8]     = *(float4*)&ca[0];
                *(float4*)&cpart[arow][aq][sub * 8 + 4] = *(float4*)&ca[4];
            }
        }
        __syncthreads();

        // ---- merge quarters: warp r (<8) handles row r ----
        if (wid < 8 && lane < 16) {
            float invZ = __fdividef(1.f, zpart[wid][0] + zpart[wid][1]
                                       + zpart[wid][2] + zpart[wid][3]);
            float4 c0 = *(float4*)&cpart[wid][0][sub * 8];
            float4 c1 = *(float4*)&cpart[wid][1][sub * 8];
            float4 c2 = *(float4*)&cpart[wid][2][sub * 8];
            float4 c3 = *(float4*)&cpart[wid][3][sub * 8];
            float4 d0 = *(float4*)&cpart[wid][0][sub * 8 + 4];
            float4 d1 = *(float4*)&cpart[wid][1][sub * 8 + 4];
            float4 d2 = *(float4*)&cpart[wid][2][sub * 8 + 4];
            float4 d3 = *(float4*)&cpart[wid][3][sub * 8 + 4];
            __half2 h0 = __floats2half2_rn((c0.x + c1.x + c2.x + c3.x) * invZ,
                                           (c0.y + c1.y + c2.y + c3.y) * invZ);
            __half2 h1 = __floats2half2_rn((c0.z + c1.z + c2.z + c3.z) * invZ,
                                           (c0.w + c1.w + c2.w + c3.w) * invZ);
            __half2 h2 = __floats2half2_rn((d0.x + d1.x + d2.x + d3.x) * invZ,
                                           (d0.y + d1.y + d2.y + d3.y) * invZ);
            __half2 h3 = __floats2half2_rn((d0.z + d1.z + d2.z + d3.z) * invZ,
                                           (d0.w + d1.w + d2.w + d3.w) * invZ);
            uint4 pk;
            pk.x = *(uint32_t*)&h0; pk.y = *(uint32_t*)&h1;
            pk.z = *(uint32_t*)&h2; pk.w = *(uint32_t*)&h3;
            *(uint4*)&ash[wid][sub * 8] = pk;
        }
        __syncthreads();

        // ---- cell HMMA: 32 warps x 2 n8-tiles, K=256, M16 (rows 8..15 zero) ----
        float acc[2][4];
        #pragma unroll
        for (int j = 0; j < 2; j++)
            #pragma unroll
            for (int q = 0; q < 4; q++) acc[j][q] = 0.f;

        #pragma unroll
        for (int kt = 0; kt < 16; kt++) {
            uint32_t a[4];
            ldmA(a, &ash[lrow][kt * 16 + lcol]);
            #pragma unroll
            for (int j = 0; j < 2; j++) {
                uint2 b = wbase[(kt * 8 + j0 + j) * 32];
                mma16816(acc[j], a, b);
            }
        }
        __syncthreads();   // mma reads of old h done before h update

        {
            float dv = (myrow < 8) ? dinsh[myrow] : 0.f;
            #pragma unroll
            for (int j = 0; j < 2; j++) {
                float t0 = __shfl_xor_sync(0xffffffffu, acc[j][0], 1);
                float t1 = __shfl_xor_sync(0xffffffffu, acc[j][1], 1);
                float t2 = __shfl_xor_sync(0xffffffffu, acc[j][2], 1);
                float t3 = __shfl_xor_sync(0xffffffffu, acc[j][3], 1);
                float gi, gf, gg, go;
                if (!odd) { gi = acc[j][0]; gf = acc[j][1]; gg = t0; go = t1; }
                else      { gi = t2; gf = t3; gg = acc[j][2]; go = acc[j][3]; }
                if (myrow < 8) {
                    int u = wq * 16 + (j0 + j) * 2 + tg2;
                    float4 bi = *(const float4*)&biassh[u * 4];
                    float4 wi = *(const float4*)&dinwsh[u * 4];
                    gi += bi.x + dv * wi.x;
                    gf += bi.y + dv * wi.y;
                    gg += bi.z + dv * wi.z;
                    go += bi.w + dv * wi.w;
                    float cn = fsig_fast(gf) * creg[j] + fsig_fast(gi) * ftanh_fast(gg);
                    creg[j] = cn;
                    float hn = fsig_fast(go) * ftanh_fast(cn);
                    hsh[myrow][u] = hn;
                    ash[myrow][128 + u] = __float2half_rn(hn);
                }
            }
        }
        __syncthreads();   // h updated; next phase1 reads hsh/ash
    }

    // final fc for last step
    if (wid >= 24) {
        int r = wid - 24;
        float s = hsh[r][lane] * fw0 + hsh[r][lane + 32] * fw1
                + hsh[r][lane + 64] * fw2 + hsh[r][lane + 96] * fw3;
        #pragma unroll
        for (int off = 16; off > 0; off >>= 1) s += __shfl_xor_sync(0xffffffffu, s, off);
        if (lane == 0)
            out[(b0 + r) * NO + (NO - 1)] = s + fcbv;
    }
}

// ------------------------- launch -------------------------
extern "C" void kernel_launch(void* const* d_in, const int* in_sizes, int n_in,
                              void* d_out, int out_size)
{
    const float* x      = (const float*)d_in[0];
    const float* encWih = (const float*)d_in[1];
    const float* encWhh = (const float*)d_in[2];
    const float* encBih = (const float*)d_in[3];
    const float* encBhh = (const float*)d_in[4];
    const float* Wa     = (const float*)d_in[5];
    const float* Ua     = (const float*)d_in[6];
    const float* va     = (const float*)d_in[7];
    const float* decWih = (const float*)d_in[8];
    const float* decWhh = (const float*)d_in[9];
    const float* decBih = (const float*)d_in[10];
    const float* decBhh = (const float*)d_in[11];
    const float* fcW    = (const float*)d_in[12];
    const float* fcb    = (const float*)d_in[13];
    float* out = (float*)d_out;

    pack_kernel<<<256, 256>>>(encWih, encWhh, encBih, encBhh, Wa, Ua,
                              decWih, decWhh, decBih, decBhh);
    enc_kernel<<<NB / 16, 256>>>(x);
    dec_kernel<<<NB / 8, 1024>>>(x, va, fcW, fcb, out);
}

// round 14
// speedup vs baseline: 1.0920x; 1.0920x over previous
#include <cuda_runtime.h>
#include <cuda_fp16.h>
#include <cstdint>

#define NB 4096
#define NT 168
#define NH 128
#define NG 512
#define NO 24

// ------------------------- device scratch -------------------------
__device__ __half g_ench[NB * NT * NH];  // encoder hidden states (B*T, H) fp16
__device__ __half g_Ueh [NB * NT * NH];  // Ua @ enc_outs        (B*T, H) fp16
__device__ float g_h  [NB * NH];
__device__ float g_c  [NB * NH];
__device__ __half g_WencP[8 * 8 * 8 * 32 * 4];  // enc Whh B-frags [wid][kt][j][lane][4]
__device__ __half g_UaP  [16 * 8 * 32 * 4];     // Ua B-frags [nt][kt][lane][4]
__device__ __half g_WaP  [16 * 8 * 32 * 4];     // Wa B-frags [nt][kt][lane][4]
__device__ __half g_WdP  [8 * 16 * 8 * 32 * 4]; // dec [Wih(ctx)|Whh] B-frags, K=256
__device__ float g_encBp[NG];           // enc bias, n = u*4+gate
__device__ float g_wihp [NG];           // enc Wih,  n = u*4+gate
__device__ float g_decBp[NG];           // dec bias, n = u*4+gate
__device__ float g_dinW [NG];           // dec Wih col 0 (din), n = u*4+gate

// fast activations
__device__ __forceinline__ float ftanh_fast(float x) { asm("tanh.approx.f32 %0, %0;" : "+f"(x)); return x; }
__device__ __forceinline__ float fsig_fast(float x)  { return 0.5f + 0.5f * ftanh_fast(0.5f * x); }
__device__ __forceinline__ __half2 htanh2(__half2 x) {
    uint32_t v = *(uint32_t*)&x;
    asm("tanh.approx.f16x2 %0, %0;" : "+r"(v));
    return *(__half2*)&v;
}

// ------------------------- mma helpers -------------------------
__device__ __forceinline__ void ldmA(uint32_t a[4], const __half* p) {
    uint32_t addr = (uint32_t)__cvta_generic_to_shared(p);
    asm volatile("ldmatrix.sync.aligned.m8n8.x4.shared.b16 {%0,%1,%2,%3}, [%4];"
        : "=r"(a[0]), "=r"(a[1]), "=r"(a[2]), "=r"(a[3]) : "r"(addr));
}
__device__ __forceinline__ void mma16816(float c[4], const uint32_t a[4], uint2 b) {
    asm volatile("mma.sync.aligned.m16n8k16.row.col.f32.f16.f16.f32 "
        "{%0,%1,%2,%3},{%4,%5,%6,%7},{%8,%9},{%0,%1,%2,%3};"
        : "+f"(c[0]), "+f"(c[1]), "+f"(c[2]), "+f"(c[3])
        : "r"(a[0]), "r"(a[1]), "r"(a[2]), "r"(a[3]), "r"(b.x), "r"(b.y));
}

// ------------------------- weight packing -------------------------
__global__ void pack_kernel(const float* __restrict__ encWih,
                            const float* __restrict__ encWhh,
                            const float* __restrict__ encBih, const float* __restrict__ encBhh,
                            const float* __restrict__ Wa, const float* __restrict__ Ua,
                            const float* __restrict__ decWih, const float* __restrict__ decWhh,
                            const float* __restrict__ decBih, const float* __restrict__ decBhh)
{
    int stride = gridDim.x * blockDim.x;
    int i0 = blockIdx.x * blockDim.x + threadIdx.x;

    for (int idx = i0; idx < 8 * 8 * 8 * 32 * 4; idx += stride) {
        int q = idx & 3, lane = (idx >> 2) & 31;
        int rest = idx >> 7;
        int j = rest & 7, kt = (rest >> 3) & 7, wid = rest >> 6;
        int g = lane >> 2, tg = lane & 3;
        int n = wid * 64 + j * 8 + g;
        int u = n >> 2, gate = n & 3;
        int k = kt * 16 + ((q < 2) ? (tg * 2 + q) : (tg * 2 + 8 + (q - 2)));
        g_WencP[idx] = __float2half_rn(encWhh[(gate * 128 + u) * NH + k]);
    }
    for (int idx = i0; idx < 8 * 16 * 8 * 32 * 4; idx += stride) {
        int q = idx & 3, lane = (idx >> 2) & 31;
        int rest = idx >> 7;
        int j = rest & 7, kt = (rest >> 3) & 15, wid = rest >> 7;
        int g = lane >> 2, tg = lane & 3;
        int n = wid * 64 + j * 8 + g;
        int u = n >> 2, gate = n & 3;
        int k = kt * 16 + ((q < 2) ? (tg * 2 + q) : (tg * 2 + 8 + (q - 2)));
        float v = (k < NH) ? decWih[(gate * 128 + u) * (NH + 1) + 1 + k]
                           : decWhh[(gate * 128 + u) * NH + (k - NH)];
        g_WdP[idx] = __float2half_rn(v);
    }
    for (int idx = i0; idx < 16 * 8 * 32 * 4; idx += stride) {
        int q = idx & 3, lane = (idx >> 2) & 31;
        int rest = idx >> 7;
        int kt = rest & 7, nt = rest >> 3;
        int g = lane >> 2, tg = lane & 3;
        int n = nt * 8 + g;
        int k = kt * 16 + ((q < 2) ? (tg * 2 + q) : (tg * 2 + 8 + (q - 2)));
        g_UaP[idx] = __float2half_rn(Ua[n * NH + k]);
        g_WaP[idx] = __float2half_rn(Wa[n * NH + k]);
    }
    for (int i = i0; i < NG; i += stride) {
        int u = i >> 2, gate = i & 3;
        g_encBp[i] = encBih[gate * 128 + u] + encBhh[gate * 128 + u];
        g_wihp[i]  = encWih[gate * 128 + u];
        g_decBp[i] = decBih[gate * 128 + u] + decBhh[gate * 128 + u];
        g_dinW[i]  = decWih[(gate * 128 + u) * (NH + 1)];
    }
}

// ------------------------- encoder (HMMA, one launch, 168 steps) -------------------------
__global__ void __launch_bounds__(256) enc_kernel(const float* __restrict__ x)
{
    __shared__ __half hsh[32][136];
    __shared__ float biassh[NG], wihsh[NG];
    int tid = threadIdx.x;
    int wid = tid >> 5, lane = tid & 31;
    int b0 = blockIdx.x * 32;
    int g = lane >> 2, tg = lane & 3, tg2 = tg >> 1;
    int odd = tg & 1;
    int lrow = lane & 15;
    int lcol = (lane >> 4) << 3;

    for (int i = tid; i < NG; i += 256) { biassh[i] = g_encBp[i]; wihsh[i] = g_wihp[i]; }
    for (int i = tid; i < 32 * 136; i += 256) ((__half*)hsh)[i] = __ushort_as_half(0);

    float cst[16];
    #pragma unroll
    for (int i = 0; i < 16; i++) cst[i] = 0.f;

    const uint2* wbase = ((const uint2*)g_WencP) + wid * 2048 + lane;
    __syncthreads();

    for (int t = 0; t < NT; t++) {
        float xv[2];
        #pragma unroll
        for (int mi = 0; mi < 2; mi++)
            xv[mi] = x[(b0 + mi * 16 + g + (odd ? 8 : 0)) * NT + t];

        float acc[2][8][4];
        #pragma unroll
        for (int mi = 0; mi < 2; mi++)
            #pragma unroll
            for (int j = 0; j < 8; j++)
                #pragma unroll
                for (int q = 0; q < 4; q++) acc[mi][j][q] = 0.f;

        #pragma unroll
        for (int kt = 0; kt < 8; kt++) {
            uint32_t a[2][4];
            #pragma unroll
            for (int mi = 0; mi < 2; mi++)
                ldmA(a[mi], &hsh[mi * 16 + lrow][kt * 16 + lcol]);
            #pragma unroll
            for (int j = 0; j < 8; j++) {
                uint2 b = wbase[(kt * 8 + j) * 32];
                mma16816(acc[0][j], a[0], b);
                mma16816(acc[1][j], a[1], b);
            }
        }
        __syncthreads();

        #pragma unroll
        for (int mi = 0; mi < 2; mi++) {
            int row = mi * 16 + g + (odd ? 8 : 0);
            #pragma unroll
            for (int j = 0; j < 8; j++) {
                float t0 = __shfl_xor_sync(0xffffffffu, acc[mi][j][0], 1);
                float t1 = __shfl_xor_sync(0xffffffffu, acc[mi][j][1], 1);
                float t2 = __shfl_xor_sync(0xffffffffu, acc[mi][j][2], 1);
                float t3 = __shfl_xor_sync(0xffffffffu, acc[mi][j][3], 1);
                float gi, gf, gg, go;
                if (!odd) { gi = acc[mi][j][0]; gf = acc[mi][j][1]; gg = t0; go = t1; }
                else      { gi = t2; gf = t3; gg = acc[mi][j][2]; go = acc[mi][j][3]; }
                int u = wid * 16 + j * 2 + tg2;
                float4 bi = *(const float4*)&biassh[u * 4];
                float4 wi = *(const float4*)&wihsh[u * 4];
                gi += bi.x + xv[mi] * wi.x;
                gf += bi.y + xv[mi] * wi.y;
                gg += bi.z + xv[mi] * wi.z;
                go += bi.w + xv[mi] * wi.w;
                float c = fsig_fast(gf) * cst[mi * 8 + j] + fsig_fast(gi) * ftanh_fast(gg);
                cst[mi * 8 + j] = c;
                float h = fsig_fast(go) * ftanh_fast(c);
                hsh[row][u] = __float2half_rn(h);
            }
        }
        __syncthreads();

        for (int i = tid; i < 512; i += 256) {
            int r = i >> 4, ch = i & 15;
            uint4 v = *(uint4*)&hsh[r][ch * 8];
            *(uint4*)&g_ench[(size_t)(b0 + r) * (NT * NH) + (size_t)t * NH + ch * 8] = v;
        }
    }
    __syncthreads();
    for (int i = tid; i < 32 * NH; i += 256) {
        int r = i >> 7, u2 = i & 127;
        g_h[(b0 + r) * NH + u2] = __half2float(hsh[r][u2]);
    }
    #pragma unroll
    for (int mi = 0; mi < 2; mi++) {
        int row = mi * 16 + g + (odd ? 8 : 0);
        #pragma unroll
        for (int j = 0; j < 8; j++) {
            int u = wid * 16 + j * 2 + tg2;
            g_c[(b0 + row) * NH + u] = cst[mi * 8 + j];
        }
    }
}

// ------------------------- Ue = enc_outs @ Ua^T (HMMA) -------------------------
__global__ void __launch_bounds__(256) ue_kernel()
{
    __shared__ __half ash[32][136];
    int tid = threadIdx.x;
    int wid = tid >> 5, lane = tid & 31;
    size_t row0 = (size_t)blockIdx.x * 32;

    for (int i = tid; i < 512; i += 256) {
        int r = i >> 4, ch = i & 15;
        *(uint4*)&ash[r][ch * 8] = *(const uint4*)&g_ench[(row0 + r) * NH + ch * 8];
    }
    __syncthreads();

    int mi = wid & 1, nw = wid >> 1;
    int lrow = lane & 15, lcol = (lane >> 4) << 3;
    float acc[4][4];
    #pragma unroll
    for (int nt = 0; nt < 4; nt++)
        #pragma unroll
        for (int q = 0; q < 4; q++) acc[nt][q] = 0.f;

    const uint2* ub = (const uint2*)g_UaP;
    #pragma unroll
    for (int kt = 0; kt < 8; kt++) {
        uint32_t a[4];
        ldmA(a, &ash[mi * 16 + lrow][kt * 16 + lcol]);
        #pragma unroll
        for (int nt = 0; nt < 4; nt++) {
            int ntg = nw * 4 + nt;
            uint2 b = ub[(ntg * 8 + kt) * 32 + lane];
            mma16816(acc[nt], a, b);
        }
    }
    __syncthreads();

    int g = lane >> 2, tg = lane & 3;
    #pragma unroll
    for (int nt = 0; nt < 4; nt++) {
        int n = (nw * 4 + nt) * 8 + tg * 2;
        *(__half2*)&ash[mi * 16 + g][n]     = __floats2half2_rn(acc[nt][0], acc[nt][1]);
        *(__half2*)&ash[mi * 16 + 8 + g][n] = __floats2half2_rn(acc[nt][2], acc[nt][3]);
    }
    __syncthreads();
    for (int i = tid; i < 512; i += 256) {
        int r = i >> 4, ch = i & 15;
        *(uint4*)&g_Ueh[(row0 + r) * NH + ch * 8] = *(uint4*)&ash[r][ch * 8];
    }
}

// ------------------------- fused decoder (2 blocks/SM for sync overlap) --------------------
// grid 1024 x 512 thr = 16 warps, 4 rows/block, 2 blocks/SM (64 regs x 512 x 2 = full RF).
// Resident: 296 blocks x 4 rows x 86KB ~ 102 MB < L2 -> L2-resident stream (R11/R12).
// q: 16 warps x 8 units HMMA. att: 4 warps/row (quarters). cell: 16 warps x 4 n8-tiles.
// fc(step-1) overlapped into merge phase on warps 4..7.
__global__ void __launch_bounds__(512, 2) dec_kernel(const float* __restrict__ x,
                                                     const float* __restrict__ va,
                                                     const float* __restrict__ fcW,
                                                     const float* __restrict__ fcb,
                                                     float* __restrict__ out)
{
    __shared__ __half ash[16][264];     // [row][ ctx fp16 | h fp16 ] rows 4..15 zero
    __shared__ float hsh[4][NH];
    __shared__ float qsh[4][NH];
    __shared__ float cpart[4][4][NH];
    __shared__ float zpart[4][4];
    __shared__ float biassh[NG], dinwsh[NG];
    __shared__ float dinsh[4];
    int tid = threadIdx.x;
    int wid = tid >> 5, lane = tid & 31;
    int b0 = blockIdx.x * 4;
    int g = lane >> 2, tg = lane & 3, tg2 = tg >> 1;
    int odd = tg & 1;
    int lrow = lane & 15;
    int lcol = (lane >> 4) << 3;
    int sub = lane & 15;
    int arow = wid >> 2, aq = wid & 3;          // att: row (0..3), T-quarter
    int grp = wid >> 1, j0 = (wid & 1) * 4;     // cell: 64-col group (0..7), 4 n8 tiles
    int myrow = g + (odd ? 8 : 0);              // cell epilogue row (valid if < 4)

    for (int i = tid; i < NG; i += 512) { biassh[i] = g_decBp[i]; dinwsh[i] = g_dinW[i]; }
    for (int i = tid; i < 16 * 264; i += 512) ((__half*)ash)[i] = __ushort_as_half(0);
    __syncthreads();
    for (int i = tid; i < 4 * NH; i += 512) {
        int r = i >> 7, k = i & 127;
        float hv = g_h[(b0 + r) * NH + k];
        hsh[r][k] = hv;
        ash[r][128 + k] = __float2half_rn(hv);
    }
    float creg[4] = {0.f, 0.f, 0.f, 0.f};
    if (myrow < 4) {
        #pragma unroll
        for (int j = 0; j < 4; j++) {
            int u = grp * 16 + (j0 + j) * 2 + tg2;
            creg[j] = g_c[(b0 + myrow) * NH + u];
        }
    }
    if (tid < 4) dinsh[tid] = x[(b0 + tid) * NT + (NT - 1)];

    float4 va0 = *(const float4*)&va[sub * 8];
    float4 va1 = *(const float4*)&va[sub * 8 + 4];
    float fw0 = fcW[lane], fw1 = fcW[lane + 32], fw2 = fcW[lane + 64], fw3 = fcW[lane + 96];
    float fcbv = fcb[0];
    const uint4* uep = (const uint4*)(g_Ueh + (size_t)(b0 + arow) * NT * NH) + lane;
    const uint4* ep  = (const uint4*)(g_ench + (size_t)(b0 + arow) * NT * NH) + lane;
    const uint2* wbase = ((const uint2*)g_WdP) + grp * 4096 + lane;
    const uint2* wap   = ((const uint2*)g_WaP);
    __syncthreads();

    for (int step = 0; step < NO; step++) {
        // ---- phase1: q-HMMA, warp w -> units [8w, 8w+8) ----
        {
            float qc[4] = {0.f, 0.f, 0.f, 0.f};
            #pragma unroll
            for (int kt = 0; kt < 8; kt++) {
                uint32_t a[4];
                ldmA(a, &ash[lrow][128 + kt * 16 + lcol]);
                uint2 b = wap[(wid * 8 + kt) * 32 + lane];
                mma16816(qc, a, b);
            }
            int m = lane >> 2;
            if (m < 4) {
                int ub = wid * 8 + (lane & 3) * 2;
                qsh[m][ub]     = qc[0];
                qsh[m][ub + 1] = qc[1];
            }
        }
        __syncthreads();

        // ---- attention: 4 warps per row, 21 pair-iters each, f16x2 energy ----
        {
            float4 qaf = *(float4*)&qsh[arow][sub * 8];
            float4 qbf = *(float4*)&qsh[arow][sub * 8 + 4];
            __half2 qh0 = __floats2half2_rn(qaf.x, qaf.y);
            __half2 qh1 = __floats2half2_rn(qaf.z, qaf.w);
            __half2 qh2 = __floats2half2_rn(qbf.x, qbf.y);
            __half2 qh3 = __floats2half2_rn(qbf.z, qbf.w);
            float ca[8];
            #pragma unroll
            for (int j = 0; j < 8; j++) ca[j] = 0.f;
            float Z = 0.f;
            int ibeg = aq * 21;
            #pragma unroll 3
            for (int i = ibeg; i < ibeg + 21; i++) {
                uint4 ue = uep[i * 32];
                uint4 en = ep[i * 32];
                __half2 t0 = htanh2(__hadd2(*(__half2*)&ue.x, qh0));
                __half2 t1 = htanh2(__hadd2(*(__half2*)&ue.y, qh1));
                __half2 t2 = htanh2(__hadd2(*(__half2*)&ue.z, qh2));
                __half2 t3 = htanh2(__hadd2(*(__half2*)&ue.w, qh3));
                float2 f0 = __half22float2(t0);
                float2 f1 = __half22float2(t1);
                float2 f2 = __half22float2(t2);
                float2 f3 = __half22float2(t3);
                float s = f0.x * va0.x + f0.y * va0.y + f1.x * va0.z + f1.y * va0.w
                        + f2.x * va1.x + f2.y * va1.y + f3.x * va1.z + f3.y * va1.w;
                s += __shfl_xor_sync(0xffffffffu, s, 8);
                s += __shfl_xor_sync(0xffffffffu, s, 4);
                s += __shfl_xor_sync(0xffffffffu, s, 2);
                s += __shfl_xor_sync(0xffffffffu, s, 1);
                float w = __expf(s);
                Z += w;
                float2 n0 = __half22float2(*(__half2*)&en.x);
                float2 n1 = __half22float2(*(__half2*)&en.y);
                float2 n2 = __half22float2(*(__half2*)&en.z);
                float2 n3 = __half22float2(*(__half2*)&en.w);
                ca[0] += w * n0.x; ca[1] += w * n0.y;
                ca[2] += w * n1.x; ca[3] += w * n1.y;
                ca[4] += w * n2.x; ca[5] += w * n2.y;
                ca[6] += w * n3.x; ca[7] += w * n3.y;
            }
            Z += __shfl_xor_sync(0xffffffffu, Z, 16);
            #pragma unroll
            for (int j = 0; j < 8; j++) ca[j] += __shfl_xor_sync(0xffffffffu, ca[j], 16);
            if (lane == 0) zpart[arow][aq] = Z;
            if (lane < 16) {
                *(float4*)&cpart[arow][aq][sub * 8]     = *(float4*)&ca[0];
                *(float4*)&cpart[arow][aq][sub * 8 + 4] = *(float4*)&ca[4];
            }
        }
        __syncthreads();

        // ---- merge (warps 0..3) || fc(step-1) (warps 4..7) ----
        if (wid < 4 && lane < 16) {
            float invZ = __fdividef(1.f, zpart[wid][0] + zpart[wid][1]
                                       + zpart[wid][2] + zpart[wid][3]);
            float4 c0 = *(float4*)&cpart[wid][0][sub * 8];
            float4 c1 = *(float4*)&cpart[wid][1][sub * 8];
            float4 c2 = *(float4*)&cpart[wid][2][sub * 8];
            float4 c3 = *(float4*)&cpart[wid][3][sub * 8];
            float4 d0 = *(float4*)&cpart[wid][0][sub * 8 + 4];
            float4 d1 = *(float4*)&cpart[wid][1][sub * 8 + 4];
            float4 d2 = *(float4*)&cpart[wid][2][sub * 8 + 4];
            float4 d3 = *(float4*)&cpart[wid][3][sub * 8 + 4];
            __half2 h0 = __floats2half2_rn((c0.x + c1.x + c2.x + c3.x) * invZ,
                                           (c0.y + c1.y + c2.y + c3.y) * invZ);
            __half2 h1 = __floats2half2_rn((c0.z + c1.z + c2.z + c3.z) * invZ,
                                           (c0.w + c1.w + c2.w + c3.w) * invZ);
            __half2 h2 = __floats2half2_rn((d0.x + d1.x + d2.x + d3.x) * invZ,
                                           (d0.y + d1.y + d2.y + d3.y) * invZ);
            __half2 h3 = __floats2half2_rn((d0.z + d1.z + d2.z + d3.z) * invZ,
                                           (d0.w + d1.w + d2.w + d3.w) * invZ);
            uint4 pk;
            pk.x = *(uint32_t*)&h0; pk.y = *(uint32_t*)&h1;
            pk.z = *(uint32_t*)&h2; pk.w = *(uint32_t*)&h3;
            *(uint4*)&ash[wid][sub * 8] = pk;
        } else if (wid >= 4 && wid < 8 && step > 0) {
            int r = wid - 4;
            float s = hsh[r][lane] * fw0 + hsh[r][lane + 32] * fw1
                    + hsh[r][lane + 64] * fw2 + hsh[r][lane + 96] * fw3;
            #pragma unroll
            for (int off = 16; off > 0; off >>= 1) s += __shfl_xor_sync(0xffffffffu, s, off);
            if (lane == 0) {
                float p = s + fcbv;
                out[(b0 + r) * NO + (step - 1)] = p;
                dinsh[r] = p;
            }
        }
        __syncthreads();

        // ---- cell HMMA: 16 warps x 4 n8-tiles, K=256, M16 (rows 4..15 zero) ----
        float acc[4][4];
        #pragma unroll
        for (int j = 0; j < 4; j++)
            #pragma unroll
            for (int q = 0; q < 4; q++) acc[j][q] = 0.f;

        #pragma unroll
        for (int kt = 0; kt < 16; kt++) {
            uint32_t a[4];
            ldmA(a, &ash[lrow][kt * 16 + lcol]);
            #pragma unroll
            for (int j = 0; j < 4; j++) {
                uint2 b = wbase[(kt * 8 + j0 + j) * 32];
                mma16816(acc[j], a, b);
            }
        }
        __syncthreads();   // mma reads of old h done before h update

        {
            float dv = (myrow < 4) ? dinsh[myrow] : 0.f;
            #pragma unroll
            for (int j = 0; j < 4; j++) {
                float t0 = __shfl_xor_sync(0xffffffffu, acc[j][0], 1);
                float t1 = __shfl_xor_sync(0xffffffffu, acc[j][1], 1);
                float t2 = __shfl_xor_sync(0xffffffffu, acc[j][2], 1);
                float t3 = __shfl_xor_sync(0xffffffffu, acc[j][3], 1);
                float gi, gf, gg, go;
                if (!odd) { gi = acc[j][0]; gf = acc[j][1]; gg = t0; go = t1; }
                else      { gi = t2; gf = t3; gg = acc[j][2]; go = acc[j][3]; }
                if (myrow < 4) {
                    int u = grp * 16 + (j0 + j) * 2 + tg2;
                    float4 bi = *(const float4*)&biassh[u * 4];
                    float4 wi = *(const float4*)&dinwsh[u * 4];
                    gi += bi.x + dv * wi.x;
                    gf += bi.y + dv * wi.y;
                    gg += bi.z + dv * wi.z;
                    go += bi.w + dv * wi.w;
                    float cn = fsig_fast(gf) * creg[j] + fsig_fast(gi) * ftanh_fast(gg);
                    creg[j] = cn;
                    float hn = fsig_fast(go) * ftanh_fast(cn);
                    hsh[myrow][u] = hn;
                    ash[myrow][128 + u] = __float2half_rn(hn);
                }
            }
        }
        __syncthreads();   // h updated; next phase1 reads ash, fc reads hsh
    }

    // final fc for last step
    if (wid >= 4 && wid < 8) {
        int r = wid - 4;
        float s = hsh[r][lane] * fw0 + hsh[r][lane + 32] * fw1
                + hsh[r][lane + 64] * fw2 + hsh[r][lane + 96] * fw3;
        #pragma unroll
        for (int off = 16; off > 0; off >>= 1) s += __shfl_xor_sync(0xffffffffu, s, off);
        if (lane == 0)
            out[(b0 + r) * NO + (NO - 1)] = s + fcbv;
    }
}

// ------------------------- launch -------------------------
extern "C" void kernel_launch(void* const* d_in, const int* in_sizes, int n_in,
                              void* d_out, int out_size)
{
    const float* x      = (const float*)d_in[0];
    const float* encWih = (const float*)d_in[1];
    const float* encWhh = (const float*)d_in[2];
    const float* encBih = (const float*)d_in[3];
    const float* encBhh = (const float*)d_in[4];
    const float* Wa     = (const float*)d_in[5];
    const float* Ua     = (const float*)d_in[6];
    const float* va     = (const float*)d_in[7];
    const float* decWih = (const float*)d_in[8];
    const float* decWhh = (const float*)d_in[9];
    const float* decBih = (const float*)d_in[10];
    const float* decBhh = (const float*)d_in[11];
    const float* fcW    = (const float*)d_in[12];
    const float* fcb    = (const float*)d_in[13];
    float* out = (float*)d_out;

    pack_kernel<<<256, 256>>>(encWih, encWhh, encBih, encBhh, Wa, Ua,
                              decWih, decWhh, decBih, decBhh);
    enc_kernel<<<NB / 32, 256>>>(x);
    ue_kernel<<<NB * NT / 32, 256>>>();
    dec_kernel<<<NB / 4, 512>>>(x, va, fcW, fcb, out);
}